// round 6
// baseline (speedup 1.0000x reference)
#include <cuda_runtime.h>
#include <math.h>

// Problem shape (fixed by dataset): B=8, T=4096, F=1024
#define B_DIM 8
#define T_DIM 4096
#define F_DIM 1024
#define F4 (F_DIM / 4)          // 256 float4 per row
#define ROWS_PER_BLK 32
#define NBLK_PER_B (T_DIM / ROWS_PER_BLK)   // 128

// Scratch (no device-memory allocations allowed). Zero-initialized at module
// load; every launch restores state to zero so graph replays are deterministic.
__device__ float g_ksum[B_DIM * F_DIM];
__device__ float g_kc[B_DIM * F_DIM];
__device__ float g_invkd[B_DIM];
__device__ int   g_len[B_DIM];
__device__ int   g_done[B_DIM];

// ---------------------------------------------------------------------------
__device__ __forceinline__ float block_reduce1(float v) {
    __shared__ float sh[8];
    #pragma unroll
    for (int o = 16; o; o >>= 1) v += __shfl_xor_sync(0xffffffffu, v, o);
    int w = threadIdx.x >> 5, l = threadIdx.x & 31;
    if (l == 0) sh[w] = v;
    __syncthreads();
    if (w == 0) {
        v = (l < 8) ? sh[l] : 0.f;
        #pragma unroll
        for (int o = 4; o; o >>= 1) v += __shfl_xor_sync(0xffffffffu, v, o);
        if (l == 0) sh[0] = v;
    }
    __syncthreads();
    float r = sh[0];
    __syncthreads();
    return r;
}

// ---------------------------------------------------------------------------
// Pass 1 (per batch): masked per-channel sum over T + per-batch stats.
// grid (NBLK_PER_B), 256 threads. Mask is a monotone prefix, so each 32-row
// block computes its valid count via ballot and runs a branch-free load loop.
// Last block of the batch (ticket) computes k_centered and 1/kd, then resets
// scratch to zero for the next graph replay.
__global__ void __launch_bounds__(256) k_reduce_fused(
        const float4* __restrict__ x,
        const int* __restrict__ mask,
        const int b) {
    const int t0 = blockIdx.x * ROWS_PER_BLK;
    const int tid = threadIdx.x;

    __shared__ int scount;
    __shared__ int slast;

    if (tid < 32) {
        int mv = mask[b * T_DIM + t0 + tid];
        unsigned bal = __ballot_sync(0xffffffffu, mv != 0);
        if (tid == 0) scount = __popc(bal);
    }
    __syncthreads();
    const int count = scount;

    if (count > 0) {
        const float4* xb = x + ((size_t)b * T_DIM + t0) * F4 + tid;
        float ax = 0.f, ay = 0.f, az = 0.f, aw = 0.f;
        #pragma unroll 8
        for (int r = 0; r < count; ++r) {
            float4 v = xb[(size_t)r * F4];
            ax += v.x; ay += v.y; az += v.z; aw += v.w;
        }
        float* dst = &g_ksum[b * F_DIM + tid * 4];
        atomicAdd(dst + 0, ax);
        atomicAdd(dst + 1, ay);
        atomicAdd(dst + 2, az);
        atomicAdd(dst + 3, aw);
        if (tid == 0) atomicAdd(&g_len[b], count);
    }

    // ---- completion ticket ----
    __threadfence();
    __syncthreads();
    if (tid == 0)
        slast = (atomicAdd(&g_done[b], 1) == NBLK_PER_B - 1) ? 1 : 0;
    __syncthreads();
    if (!slast) return;

    // ---- last block: per-batch stats ----
    const float L = (float)g_len[b];
    const float invL = 1.0f / L;

    float kv[4];
    float s = 0.f;
    #pragma unroll
    for (int j = 0; j < 4; ++j) {
        kv[j] = g_ksum[b * F_DIM + tid * 4 + j] * invL;
        s += kv[j];
    }
    float meank = block_reduce1(s) * (1.0f / (float)F_DIM);

    float ss = 0.f;
    #pragma unroll
    for (int j = 0; j < 4; ++j) {
        float kc = kv[j] - meank;
        g_kc[b * F_DIM + tid * 4 + j] = kc;
        ss += kc * kc;
        g_ksum[b * F_DIM + tid * 4 + j] = 0.0f;   // restore for next replay
    }
    float kd2 = block_reduce1(ss);
    if (tid == 0) {
        g_invkd[b] = rsqrtf(kd2);
        g_len[b] = 0;
        g_done[b] = 0;
    }
}

// ---------------------------------------------------------------------------
// Pass 3 (per batch): WARP-PER-ROW output. Block = 256 threads = 8 rows.
// Runs right after this batch's pass 1, so the 16 MB batch slice of x is
// L2-resident — reads are mostly L2 hits. Forward order. 48 regs, MLP=8.
__global__ void __launch_bounds__(256) pfsa_out_kernel(
        const float4* __restrict__ x,
        const int* __restrict__ mask,
        float4* __restrict__ out,
        const int b) {
    const int warp = threadIdx.x >> 5;
    const int lane = threadIdx.x & 31;

    const int t = blockIdx.x * 8 + warp;
    const size_t base = ((size_t)b * T_DIM + t) * F4;

    if (!mask[b * T_DIM + t]) {
        const float4 z = make_float4(0.f, 0.f, 0.f, 0.f);
        #pragma unroll
        for (int j = 0; j < 8; ++j)
            __stcs(&out[base + lane + j * 32], z);
        return;
    }

    // Front-batched x loads: 8 independent float4 (last use -> .cs)
    float4 v[8];
    #pragma unroll
    for (int j = 0; j < 8; ++j) v[j] = __ldcs(&x[base + lane + j * 32]);

    float s1 = 0.f, s2 = 0.f;
    #pragma unroll
    for (int j = 0; j < 8; ++j) {
        s1 += v[j].x + v[j].y + v[j].z + v[j].w;
        s2 += v[j].x * v[j].x + v[j].y * v[j].y + v[j].z * v[j].z + v[j].w * v[j].w;
    }

    // kc dot in two 4-wide chunks (kc: 4 KB/batch, L1/L2-resident)
    const float4* kcb = (const float4*)&g_kc[b * F_DIM];
    float s3 = 0.f;
    #pragma unroll
    for (int h = 0; h < 2; ++h) {
        float4 kc[4];
        #pragma unroll
        for (int j = 0; j < 4; ++j) kc[j] = kcb[lane + (h * 4 + j) * 32];
        #pragma unroll
        for (int j = 0; j < 4; ++j) {
            const float4& w = v[h * 4 + j];
            s3 += w.x * kc[j].x + w.y * kc[j].y + w.z * kc[j].z + w.w * kc[j].w;
        }
    }

    #pragma unroll
    for (int o = 16; o; o >>= 1) {
        s1 += __shfl_xor_sync(0xffffffffu, s1, o);
        s2 += __shfl_xor_sync(0xffffffffu, s2, o);
        s3 += __shfl_xor_sync(0xffffffffu, s3, o);
    }

    float qd2 = s2 - s1 * s1 * (1.0f / (float)F_DIM);
    float C = s3 * rsqrtf(qd2) * g_invkd[b];
    float A = 1.0f / (1.0f + __expf(C));   // (1 - sigmoid(C))^ALPHA, ALPHA=1

    #pragma unroll
    for (int j = 0; j < 8; ++j) {
        v[j].x *= A; v[j].y *= A; v[j].z *= A; v[j].w *= A;
        __stcs(&out[base + lane + j * 32], v[j]);
    }
}

// ---------------------------------------------------------------------------
// Per-batch software pipeline across two streams (fork/join via events, all
// graph-capturable):   side stream: reduce(0) reduce(1) ... reduce(7)
//                      main stream: pfsa(0) pfsa(1) ... pfsa(7)
// pfsa(b) waits on reduce(b)'s event; reduce(b+1) overlaps pfsa(b), keeping
// HBM saturated and serving pfsa's x reads from L2 (batch slice = 16 MB).
extern "C" void kernel_launch(void* const* d_in, const int* in_sizes, int n_in,
                              void* d_out, int out_size) {
    const float4* x = (const float4*)d_in[0];
    const int* mask = (const int*)d_in[1];
    float4* out = (float4*)d_out;

    // One-time handle creation (host-side only; no device memory).
    static cudaStream_t s_side = nullptr;
    static cudaEvent_t ev_fork = nullptr;
    static cudaEvent_t ev_red[B_DIM];
    if (!s_side) {
        cudaStreamCreateWithFlags(&s_side, cudaStreamNonBlocking);
        cudaEventCreateWithFlags(&ev_fork, cudaEventDisableTiming);
        for (int b = 0; b < B_DIM; ++b)
            cudaEventCreateWithFlags(&ev_red[b], cudaEventDisableTiming);
    }

    // Fork: side stream joins the capture by waiting on main-stream event.
    cudaEventRecord(ev_fork, 0);
    cudaStreamWaitEvent(s_side, ev_fork, 0);

    for (int b = 0; b < B_DIM; ++b) {
        k_reduce_fused<<<NBLK_PER_B, 256, 0, s_side>>>(x, mask, b);
        cudaEventRecord(ev_red[b], s_side);
        // pfsa(b) on main stream, gated on this batch's reduce.
        cudaStreamWaitEvent(0, ev_red[b], 0);
        pfsa_out_kernel<<<T_DIM / 8, 256>>>(x, mask, out, b);
    }
    // Join is implicit: main's last pfsa waits ev_red[7], which follows all
    // side-stream work in order.
}

// round 7
// speedup vs baseline: 2.3963x; 2.3963x over previous
#include <cuda_runtime.h>
#include <math.h>

// Problem shape (fixed by dataset): B=8, T=4096, F=1024
#define B_DIM 8
#define T_DIM 4096
#define F_DIM 1024
#define F4 (F_DIM / 4)          // 256 float4 per row
#define ROWS_PER_BLK 16
#define NBLK_PER_B (T_DIM / ROWS_PER_BLK)   // 256

// Scratch (no device-memory allocations allowed). Zero-initialized at module
// load; every launch restores state to zero so graph replays are deterministic.
__device__ float g_ksum[B_DIM * F_DIM];
__device__ float g_kc[B_DIM * F_DIM];
__device__ float g_invkd[B_DIM];
__device__ int   g_len[B_DIM];
__device__ int   g_done[B_DIM];

// ---------------------------------------------------------------------------
__device__ __forceinline__ float block_reduce1(float v) {
    __shared__ float sh[8];
    #pragma unroll
    for (int o = 16; o; o >>= 1) v += __shfl_xor_sync(0xffffffffu, v, o);
    int w = threadIdx.x >> 5, l = threadIdx.x & 31;
    if (l == 0) sh[w] = v;
    __syncthreads();
    if (w == 0) {
        v = (l < 8) ? sh[l] : 0.f;
        #pragma unroll
        for (int o = 4; o; o >>= 1) v += __shfl_xor_sync(0xffffffffu, v, o);
        if (l == 0) sh[0] = v;
    }
    __syncthreads();
    float r = sh[0];
    __syncthreads();
    return r;
}

// ---------------------------------------------------------------------------
// Kernel 1 (fused): masked per-channel sum over T + per-batch stats.
// grid (NBLK_PER_B, B), 256 threads, 16 rows per block (2048 blocks total for
// high occupancy). Mask is a monotone prefix, so each block gets its valid
// count via ballot and runs a branch-free load loop. The last block of each
// batch (ticket) computes k_centered and 1/kd, then resets scratch to zero.
__global__ void __launch_bounds__(256) k_reduce_fused(
        const float4* __restrict__ x,
        const int* __restrict__ mask) {
    const int b = blockIdx.y;
    const int t0 = blockIdx.x * ROWS_PER_BLK;
    const int tid = threadIdx.x;

    __shared__ int scount;
    __shared__ int slast;

    if (tid < 32) {
        int r = tid & 15;
        int mv = mask[b * T_DIM + t0 + r];
        unsigned bal = __ballot_sync(0xffffffffu, mv != 0) & 0xffffu;
        if (tid == 0) scount = __popc(bal);
    }
    __syncthreads();
    const int count = scount;

    if (count > 0) {
        const float4* xb = x + ((size_t)b * T_DIM + t0) * F4 + tid;
        float ax = 0.f, ay = 0.f, az = 0.f, aw = 0.f;
        #pragma unroll 8
        for (int r = 0; r < count; ++r) {
            float4 v = xb[(size_t)r * F4];
            ax += v.x; ay += v.y; az += v.z; aw += v.w;
        }
        float* dst = &g_ksum[b * F_DIM + tid * 4];
        atomicAdd(dst + 0, ax);
        atomicAdd(dst + 1, ay);
        atomicAdd(dst + 2, az);
        atomicAdd(dst + 3, aw);
        if (tid == 0) atomicAdd(&g_len[b], count);
    }

    // ---- completion ticket ----
    __threadfence();
    __syncthreads();
    if (tid == 0)
        slast = (atomicAdd(&g_done[b], 1) == NBLK_PER_B - 1) ? 1 : 0;
    __syncthreads();
    if (!slast) return;

    // ---- last block of this batch: per-batch stats ----
    const float L = (float)g_len[b];
    const float invL = 1.0f / L;

    float kv[4];
    float s = 0.f;
    #pragma unroll
    for (int j = 0; j < 4; ++j) {
        kv[j] = g_ksum[b * F_DIM + tid * 4 + j] * invL;
        s += kv[j];
    }
    float meank = block_reduce1(s) * (1.0f / (float)F_DIM);

    float ss = 0.f;
    #pragma unroll
    for (int j = 0; j < 4; ++j) {
        float kc = kv[j] - meank;
        g_kc[b * F_DIM + tid * 4 + j] = kc;
        ss += kc * kc;
        g_ksum[b * F_DIM + tid * 4 + j] = 0.0f;   // restore for next replay
    }
    float kd2 = block_reduce1(ss);
    if (tid == 0) {
        g_invkd[b] = rsqrtf(kd2);
        g_len[b] = 0;
        g_done[b] = 0;
    }
}

// ---------------------------------------------------------------------------
// Kernel 2: WARP-PER-ROW output pass (exact R5 version — 32.4us measured).
// Block = 256 threads = 8 warps = 8 rows. Reverse global row order to reuse
// the x tail kernel 1 left in L2. No occupancy clamp: 48 regs keeps all 8
// x-loads in flight (MLP beats occupancy here).
__global__ void __launch_bounds__(256) pfsa_out_kernel(
        const float4* __restrict__ x,
        const int* __restrict__ mask,
        float4* __restrict__ out) {
    const int warp = threadIdx.x >> 5;
    const int lane = threadIdx.x & 31;

    const int row = (B_DIM * T_DIM - 1) - (blockIdx.x * 8 + warp);
    const int b = row >> 12;            // row / T_DIM
    const int t = row & (T_DIM - 1);    // row % T_DIM

    const size_t base = (size_t)row * F4;

    if (!mask[b * T_DIM + t]) {
        const float4 z = make_float4(0.f, 0.f, 0.f, 0.f);
        #pragma unroll
        for (int j = 0; j < 8; ++j)
            __stcs(&out[base + lane + j * 32], z);
        return;
    }

    // Front-batched x loads: 8 independent float4 (last use -> .cs)
    float4 v[8];
    #pragma unroll
    for (int j = 0; j < 8; ++j) v[j] = __ldcs(&x[base + lane + j * 32]);

    float s1 = 0.f, s2 = 0.f;
    #pragma unroll
    for (int j = 0; j < 8; ++j) {
        s1 += v[j].x + v[j].y + v[j].z + v[j].w;
        s2 += v[j].x * v[j].x + v[j].y * v[j].y + v[j].z * v[j].z + v[j].w * v[j].w;
    }

    // kc dot in two 4-wide chunks (kc: 4 KB/batch, L1/L2-resident)
    const float4* kcb = (const float4*)&g_kc[b * F_DIM];
    float s3 = 0.f;
    #pragma unroll
    for (int h = 0; h < 2; ++h) {
        float4 kc[4];
        #pragma unroll
        for (int j = 0; j < 4; ++j) kc[j] = kcb[lane + (h * 4 + j) * 32];
        #pragma unroll
        for (int j = 0; j < 4; ++j) {
            const float4& w = v[h * 4 + j];
            s3 += w.x * kc[j].x + w.y * kc[j].y + w.z * kc[j].z + w.w * kc[j].w;
        }
    }

    #pragma unroll
    for (int o = 16; o; o >>= 1) {
        s1 += __shfl_xor_sync(0xffffffffu, s1, o);
        s2 += __shfl_xor_sync(0xffffffffu, s2, o);
        s3 += __shfl_xor_sync(0xffffffffu, s3, o);
    }

    float qd2 = s2 - s1 * s1 * (1.0f / (float)F_DIM);
    float C = s3 * rsqrtf(qd2) * g_invkd[b];
    float A = 1.0f / (1.0f + __expf(C));   // (1 - sigmoid(C))^ALPHA, ALPHA=1

    #pragma unroll
    for (int j = 0; j < 8; ++j) {
        v[j].x *= A; v[j].y *= A; v[j].z *= A; v[j].w *= A;
        __stcs(&out[base + lane + j * 32], v[j]);
    }
}

// ---------------------------------------------------------------------------
extern "C" void kernel_launch(void* const* d_in, const int* in_sizes, int n_in,
                              void* d_out, int out_size) {
    const float4* x = (const float4*)d_in[0];
    const int* mask = (const int*)d_in[1];
    float4* out = (float4*)d_out;

    dim3 g1(NBLK_PER_B, B_DIM);
    k_reduce_fused<<<g1, 256>>>(x, mask);

    pfsa_out_kernel<<<(B_DIM * T_DIM) / 8, 256>>>(x, mask, out);
}

// round 8
// speedup vs baseline: 2.6483x; 1.1052x over previous
#include <cuda_runtime.h>
#include <math.h>

// Problem shape (fixed by dataset): B=8, T=4096, F=1024
#define B_DIM 8
#define T_DIM 4096
#define F_DIM 1024
#define F4 (F_DIM / 4)          // 256 float4 per row
#define ROWS_PER_BLK 32
#define NBLK_PER_B (T_DIM / ROWS_PER_BLK)     // 128
#define RED_BLOCKS (B_DIM * NBLK_PER_B)       // 1024 producer blocks
#define OUT_ROWS_PER_BLK 8
#define OUT_BLK_PER_B (T_DIM / OUT_ROWS_PER_BLK)   // 512
#define OUT_BLOCKS (B_DIM * OUT_BLK_PER_B)         // 4096 consumer blocks

// Scratch (no device-memory allocations allowed). Zero-initialized at module
// load; every launch restores state to zero so graph replays are deterministic.
__device__ float g_ksum[B_DIM * F_DIM];
__device__ float g_kc[B_DIM * F_DIM];
__device__ float g_invkd[B_DIM];
__device__ int   g_len[B_DIM];
__device__ int   g_done[B_DIM];
__device__ int   g_ready[B_DIM];   // set by last producer block of batch b
__device__ int   g_cdone[B_DIM];   // consumer completion counter (resets g_ready)

// ---------------------------------------------------------------------------
__device__ __forceinline__ float block_reduce1(float v) {
    __shared__ float sh[8];
    #pragma unroll
    for (int o = 16; o; o >>= 1) v += __shfl_xor_sync(0xffffffffu, v, o);
    int w = threadIdx.x >> 5, l = threadIdx.x & 31;
    if (l == 0) sh[w] = v;
    __syncthreads();
    if (w == 0) {
        v = (l < 8) ? sh[l] : 0.f;
        #pragma unroll
        for (int o = 4; o; o >>= 1) v += __shfl_xor_sync(0xffffffffu, v, o);
        if (l == 0) sh[0] = v;
    }
    __syncthreads();
    float r = sh[0];
    __syncthreads();
    return r;
}

// ---------------------------------------------------------------------------
// Producer path: masked per-channel sum over 32 rows, atomics into g_ksum.
// Last block of the batch computes k_centered / 1/kd, restores scratch, and
// raises g_ready[b].
__device__ __forceinline__ void producer(const float4* __restrict__ x,
                                         const int* __restrict__ mask,
                                         int rbid) {
    const int b = rbid >> 7;                    // rbid / NBLK_PER_B
    const int t0 = (rbid & 127) * ROWS_PER_BLK;
    const int tid = threadIdx.x;

    __shared__ int scount;
    __shared__ int slast;

    if (tid < 32) {
        int mv = mask[b * T_DIM + t0 + tid];
        unsigned bal = __ballot_sync(0xffffffffu, mv != 0);
        if (tid == 0) scount = __popc(bal);
    }
    __syncthreads();
    const int count = scount;

    if (count > 0) {
        const float4* xb = x + ((size_t)b * T_DIM + t0) * F4 + tid;
        float ax = 0.f, ay = 0.f, az = 0.f, aw = 0.f;
        #pragma unroll 8
        for (int r = 0; r < count; ++r) {
            float4 v = xb[(size_t)r * F4];
            ax += v.x; ay += v.y; az += v.z; aw += v.w;
        }
        float* dst = &g_ksum[b * F_DIM + tid * 4];
        atomicAdd(dst + 0, ax);
        atomicAdd(dst + 1, ay);
        atomicAdd(dst + 2, az);
        atomicAdd(dst + 3, aw);
        if (tid == 0) atomicAdd(&g_len[b], count);
    }

    // ---- completion ticket ----
    __threadfence();
    __syncthreads();
    if (tid == 0)
        slast = (atomicAdd(&g_done[b], 1) == NBLK_PER_B - 1) ? 1 : 0;
    __syncthreads();
    if (!slast) return;

    // ---- last block of this batch: per-batch stats ----
    const float L = (float)g_len[b];
    const float invL = 1.0f / L;

    float kv[4];
    float s = 0.f;
    #pragma unroll
    for (int j = 0; j < 4; ++j) {
        kv[j] = g_ksum[b * F_DIM + tid * 4 + j] * invL;
        s += kv[j];
    }
    float meank = block_reduce1(s) * (1.0f / (float)F_DIM);

    float ss = 0.f;
    #pragma unroll
    for (int j = 0; j < 4; ++j) {
        float kc = kv[j] - meank;
        g_kc[b * F_DIM + tid * 4 + j] = kc;
        ss += kc * kc;
        g_ksum[b * F_DIM + tid * 4 + j] = 0.0f;   // restore for next replay
    }
    float kd2 = block_reduce1(ss);
    if (tid == 0) {
        g_invkd[b] = rsqrtf(kd2);
        g_len[b] = 0;
        g_done[b] = 0;
        __threadfence();                 // publish stats before raising flag
        atomicExch(&g_ready[b], 1);
    }
}

// ---------------------------------------------------------------------------
// Consumer path: WARP-PER-ROW output over 8 consecutive rows of one batch.
// Spins on g_ready[b] only if its first row is valid (mask is a monotone
// prefix, so mask[t0]==0 => whole block is padding: write zeros, no wait).
__device__ __forceinline__ void consumer(const float4* __restrict__ x,
                                         const int* __restrict__ mask,
                                         float4* __restrict__ out,
                                         int cbid) {
    const int b = cbid / OUT_BLK_PER_B;
    const int t0 = (cbid % OUT_BLK_PER_B) * OUT_ROWS_PER_BLK;
    const int warp = threadIdx.x >> 5;
    const int lane = threadIdx.x & 31;
    const int tid = threadIdx.x;

    const int t = t0 + warp;
    const size_t base = ((size_t)b * T_DIM + t) * F4;

    const int firstValid = mask[b * T_DIM + t0];

    if (firstValid) {
        if (tid == 0) {
            while (atomicAdd(&g_ready[b], 0) == 0) __nanosleep(128);
        }
        __syncthreads();
        __threadfence();   // order subsequent kc/invkd reads after flag
    }

    if (!mask[b * T_DIM + t]) {
        const float4 z = make_float4(0.f, 0.f, 0.f, 0.f);
        #pragma unroll
        for (int j = 0; j < 8; ++j)
            __stcs(&out[base + lane + j * 32], z);
    } else {
        // Front-batched x loads: 8 independent float4 (last use -> .cs)
        float4 v[8];
        #pragma unroll
        for (int j = 0; j < 8; ++j) v[j] = __ldcs(&x[base + lane + j * 32]);

        float s1 = 0.f, s2 = 0.f;
        #pragma unroll
        for (int j = 0; j < 8; ++j) {
            s1 += v[j].x + v[j].y + v[j].z + v[j].w;
            s2 += v[j].x * v[j].x + v[j].y * v[j].y + v[j].z * v[j].z + v[j].w * v[j].w;
        }

        const float4* kcb = (const float4*)&g_kc[b * F_DIM];
        float s3 = 0.f;
        #pragma unroll
        for (int h = 0; h < 2; ++h) {
            float4 kc[4];
            #pragma unroll
            for (int j = 0; j < 4; ++j) kc[j] = kcb[lane + (h * 4 + j) * 32];
            #pragma unroll
            for (int j = 0; j < 4; ++j) {
                const float4& w = v[h * 4 + j];
                s3 += w.x * kc[j].x + w.y * kc[j].y + w.z * kc[j].z + w.w * kc[j].w;
            }
        }

        #pragma unroll
        for (int o = 16; o; o >>= 1) {
            s1 += __shfl_xor_sync(0xffffffffu, s1, o);
            s2 += __shfl_xor_sync(0xffffffffu, s2, o);
            s3 += __shfl_xor_sync(0xffffffffu, s3, o);
        }

        float qd2 = s2 - s1 * s1 * (1.0f / (float)F_DIM);
        float C = s3 * rsqrtf(qd2) * g_invkd[b];
        float A = 1.0f / (1.0f + __expf(C));   // (1 - sigmoid(C))^ALPHA

        #pragma unroll
        for (int j = 0; j < 8; ++j) {
            v[j].x *= A; v[j].y *= A; v[j].z *= A; v[j].w *= A;
            __stcs(&out[base + lane + j * 32], v[j]);
        }
    }

    // ---- reset ticket: last consumer of batch b restores g_ready/g_cdone ----
    __syncthreads();
    if (tid == 0) {
        if (atomicAdd(&g_cdone[b], 1) == OUT_BLK_PER_B - 1) {
            g_cdone[b] = 0;
            atomicExch(&g_ready[b], 0);
        }
    }
}

// ---------------------------------------------------------------------------
// Single fused kernel. Producers occupy bids [0, RED_BLOCKS) and are therefore
// dispatched before every consumer (bid-ordered CTA dispatch), so consumer
// spin-waits cannot starve producers. Consumers of batch b start as soon as
// that batch's stats land -> the two memory phases overlap.
__global__ void __launch_bounds__(256) pfsa_fused_kernel(
        const float4* __restrict__ x,
        const int* __restrict__ mask,
        float4* __restrict__ out) {
    const int bid = blockIdx.x;
    if (bid < RED_BLOCKS)
        producer(x, mask, bid);
    else
        consumer(x, mask, out, bid - RED_BLOCKS);
}

// ---------------------------------------------------------------------------
extern "C" void kernel_launch(void* const* d_in, const int* in_sizes, int n_in,
                              void* d_out, int out_size) {
    const float4* x = (const float4*)d_in[0];
    const int* mask = (const int*)d_in[1];
    float4* out = (float4*)d_out;

    pfsa_fused_kernel<<<RED_BLOCKS + OUT_BLOCKS, 256>>>(x, mask, out);
}

// round 9
// speedup vs baseline: 2.6527x; 1.0017x over previous
#include <cuda_runtime.h>
#include <math.h>

// Problem shape (fixed by dataset): B=8, T=4096, F=1024
#define B_DIM 8
#define T_DIM 4096
#define F_DIM 1024
#define F4 (F_DIM / 4)          // 256 float4 per row
#define ROWS_PER_BLK 32
#define NBLK_PER_B (T_DIM / ROWS_PER_BLK)   // 128

// Scratch (no device-memory allocations allowed). Zero-initialized at module
// load; every launch restores state to zero so graph replays are deterministic.
__device__ float g_ksum[B_DIM * F_DIM];
__device__ float g_kc[B_DIM * F_DIM];
__device__ float g_invkd[B_DIM];
__device__ int   g_len[B_DIM];
__device__ int   g_done[B_DIM];

// ---------------------------------------------------------------------------
__device__ __forceinline__ float block_reduce1(float v) {
    __shared__ float sh[8];
    #pragma unroll
    for (int o = 16; o; o >>= 1) v += __shfl_xor_sync(0xffffffffu, v, o);
    int w = threadIdx.x >> 5, l = threadIdx.x & 31;
    if (l == 0) sh[w] = v;
    __syncthreads();
    if (w == 0) {
        v = (l < 8) ? sh[l] : 0.f;
        #pragma unroll
        for (int o = 4; o; o >>= 1) v += __shfl_xor_sync(0xffffffffu, v, o);
        if (l == 0) sh[0] = v;
    }
    __syncthreads();
    float r = sh[0];
    __syncthreads();
    return r;
}

// ---------------------------------------------------------------------------
// Kernel A (side stream, concurrent with reduce): zero-fill padded rows.
// grid (T/8, B), 256 threads = 8 warps = 8 rows. Warp stores zeros iff its
// row is padding. Valid-row warps exit immediately (~75% of them).
__global__ void __launch_bounds__(256) zero_pad_kernel(
        const int* __restrict__ mask,
        float4* __restrict__ out) {
    const int warp = threadIdx.x >> 5;
    const int lane = threadIdx.x & 31;
    const int b = blockIdx.y;
    const int t = blockIdx.x * 8 + warp;

    if (mask[b * T_DIM + t]) return;

    const size_t base = ((size_t)b * T_DIM + t) * F4;
    const float4 z = make_float4(0.f, 0.f, 0.f, 0.f);
    #pragma unroll
    for (int j = 0; j < 8; ++j)
        __stcs(&out[base + lane + j * 32], z);
}

// ---------------------------------------------------------------------------
// Kernel B (main stream): masked per-channel sum over T + per-batch stats.
// grid (NBLK_PER_B, B), 256 threads, 32 rows/block (R5 config — best measured).
// Ticketed last block computes k_centered and 1/kd, restores scratch to zero.
__global__ void __launch_bounds__(256) k_reduce_fused(
        const float4* __restrict__ x,
        const int* __restrict__ mask) {
    const int b = blockIdx.y;
    const int t0 = blockIdx.x * ROWS_PER_BLK;
    const int tid = threadIdx.x;

    __shared__ int scount;
    __shared__ int slast;

    if (tid < 32) {
        int mv = mask[b * T_DIM + t0 + tid];
        unsigned bal = __ballot_sync(0xffffffffu, mv != 0);
        if (tid == 0) scount = __popc(bal);
    }
    __syncthreads();
    const int count = scount;

    if (count > 0) {
        const float4* xb = x + ((size_t)b * T_DIM + t0) * F4 + tid;
        float ax = 0.f, ay = 0.f, az = 0.f, aw = 0.f;
        #pragma unroll 8
        for (int r = 0; r < count; ++r) {
            float4 v = xb[(size_t)r * F4];
            ax += v.x; ay += v.y; az += v.z; aw += v.w;
        }
        float* dst = &g_ksum[b * F_DIM + tid * 4];
        atomicAdd(dst + 0, ax);
        atomicAdd(dst + 1, ay);
        atomicAdd(dst + 2, az);
        atomicAdd(dst + 3, aw);
        if (tid == 0) atomicAdd(&g_len[b], count);
    }

    // ---- completion ticket ----
    __threadfence();
    __syncthreads();
    if (tid == 0)
        slast = (atomicAdd(&g_done[b], 1) == NBLK_PER_B - 1) ? 1 : 0;
    __syncthreads();
    if (!slast) return;

    // ---- last block of this batch: per-batch stats ----
    const float L = (float)g_len[b];
    const float invL = 1.0f / L;

    float kv[4];
    float s = 0.f;
    #pragma unroll
    for (int j = 0; j < 4; ++j) {
        kv[j] = g_ksum[b * F_DIM + tid * 4 + j] * invL;
        s += kv[j];
    }
    float meank = block_reduce1(s) * (1.0f / (float)F_DIM);

    float ss = 0.f;
    #pragma unroll
    for (int j = 0; j < 4; ++j) {
        float kc = kv[j] - meank;
        g_kc[b * F_DIM + tid * 4 + j] = kc;
        ss += kc * kc;
        g_ksum[b * F_DIM + tid * 4 + j] = 0.0f;   // restore for next replay
    }
    float kd2 = block_reduce1(ss);
    if (tid == 0) {
        g_invkd[b] = rsqrtf(kd2);
        g_len[b] = 0;
        g_done[b] = 0;
    }
}

// ---------------------------------------------------------------------------
// Kernel C (main stream): WARP-PER-ROW output over VALID rows only; padded
// rows were zero-filled concurrently by kernel A. Reverse global order to
// reuse the x tail kernel B left in L2. 48 regs, MLP=8 (best measured).
__global__ void __launch_bounds__(256) pfsa_out_kernel(
        const float4* __restrict__ x,
        const int* __restrict__ mask,
        float4* __restrict__ out) {
    const int warp = threadIdx.x >> 5;
    const int lane = threadIdx.x & 31;

    const int row = (B_DIM * T_DIM - 1) - (blockIdx.x * 8 + warp);
    const int b = row >> 12;            // row / T_DIM
    const int t = row & (T_DIM - 1);    // row % T_DIM

    if (!mask[b * T_DIM + t]) return;   // padding handled by zero_pad_kernel

    const size_t base = (size_t)row * F4;

    // Front-batched x loads: 8 independent float4 (last use -> .cs)
    float4 v[8];
    #pragma unroll
    for (int j = 0; j < 8; ++j) v[j] = __ldcs(&x[base + lane + j * 32]);

    float s1 = 0.f, s2 = 0.f;
    #pragma unroll
    for (int j = 0; j < 8; ++j) {
        s1 += v[j].x + v[j].y + v[j].z + v[j].w;
        s2 += v[j].x * v[j].x + v[j].y * v[j].y + v[j].z * v[j].z + v[j].w * v[j].w;
    }

    // kc dot in two 4-wide chunks (kc: 4 KB/batch, L1/L2-resident)
    const float4* kcb = (const float4*)&g_kc[b * F_DIM];
    float s3 = 0.f;
    #pragma unroll
    for (int h = 0; h < 2; ++h) {
        float4 kc[4];
        #pragma unroll
        for (int j = 0; j < 4; ++j) kc[j] = kcb[lane + (h * 4 + j) * 32];
        #pragma unroll
        for (int j = 0; j < 4; ++j) {
            const float4& w = v[h * 4 + j];
            s3 += w.x * kc[j].x + w.y * kc[j].y + w.z * kc[j].z + w.w * kc[j].w;
        }
    }

    #pragma unroll
    for (int o = 16; o; o >>= 1) {
        s1 += __shfl_xor_sync(0xffffffffu, s1, o);
        s2 += __shfl_xor_sync(0xffffffffu, s2, o);
        s3 += __shfl_xor_sync(0xffffffffu, s3, o);
    }

    float qd2 = s2 - s1 * s1 * (1.0f / (float)F_DIM);
    float C = s3 * rsqrtf(qd2) * g_invkd[b];
    float A = 1.0f / (1.0f + __expf(C));   // (1 - sigmoid(C))^ALPHA, ALPHA=1

    #pragma unroll
    for (int j = 0; j < 8; ++j) {
        v[j].x *= A; v[j].y *= A; v[j].z *= A; v[j].w *= A;
        __stcs(&out[base + lane + j * 32], v[j]);
    }
}

// ---------------------------------------------------------------------------
// Schedule:  main:  reduce ─────────► pfsa(valid rows) ──► (wait side)
//            side:  zero_pad(padded rows)  [concurrent with reduce]
// Both side and main kernels are chip-filling; they co-saturate HBM.
extern "C" void kernel_launch(void* const* d_in, const int* in_sizes, int n_in,
                              void* d_out, int out_size) {
    const float4* x = (const float4*)d_in[0];
    const int* mask = (const int*)d_in[1];
    float4* out = (float4*)d_out;

    static cudaStream_t s_side = nullptr;
    static cudaEvent_t ev_fork = nullptr, ev_side = nullptr;
    if (!s_side) {
        cudaStreamCreateWithFlags(&s_side, cudaStreamNonBlocking);
        cudaEventCreateWithFlags(&ev_fork, cudaEventDisableTiming);
        cudaEventCreateWithFlags(&ev_side, cudaEventDisableTiming);
    }

    // Fork side stream off the capture origin.
    cudaEventRecord(ev_fork, 0);
    cudaStreamWaitEvent(s_side, ev_fork, 0);

    // Side: zero-fill padded rows (independent of the reduce).
    dim3 gz(T_DIM / 8, B_DIM);
    zero_pad_kernel<<<gz, 256, 0, s_side>>>(mask, out);
    cudaEventRecord(ev_side, s_side);

    // Main: reduce, then valid-row output pass.
    dim3 g1(NBLK_PER_B, B_DIM);
    k_reduce_fused<<<g1, 256>>>(x, mask);
    pfsa_out_kernel<<<(B_DIM * T_DIM) / 8, 256>>>(x, mask, out);

    // Join side back into the origin stream (required to end capture).
    cudaStreamWaitEvent(0, ev_side, 0);
}

// round 10
// speedup vs baseline: 2.7509x; 1.0370x over previous
#include <cuda_runtime.h>
#include <math.h>

// Problem shape (fixed by dataset): B=8, T=4096, F=1024
#define B_DIM 8
#define T_DIM 4096
#define F_DIM 1024
#define F4 (F_DIM / 4)          // 256 float4 per row
#define ROWS_PER_BLK 32
#define NBLK_PER_B (T_DIM / ROWS_PER_BLK)   // 128

// Scratch (no device-memory allocations allowed). Zero-initialized at module
// load; every launch restores state to zero so graph replays are deterministic.
__device__ float g_ksum[B_DIM * F_DIM];
__device__ float g_kc[B_DIM * F_DIM];
__device__ float g_invkd[B_DIM];
__device__ int   g_len[B_DIM];
__device__ int   g_done[B_DIM];

// ---------------------------------------------------------------------------
__device__ __forceinline__ float block_reduce1(float v) {
    __shared__ float sh[8];
    #pragma unroll
    for (int o = 16; o; o >>= 1) v += __shfl_xor_sync(0xffffffffu, v, o);
    int w = threadIdx.x >> 5, l = threadIdx.x & 31;
    if (l == 0) sh[w] = v;
    __syncthreads();
    if (w == 0) {
        v = (l < 8) ? sh[l] : 0.f;
        #pragma unroll
        for (int o = 4; o; o >>= 1) v += __shfl_xor_sync(0xffffffffu, v, o);
        if (l == 0) sh[0] = v;
    }
    __syncthreads();
    float r = sh[0];
    __syncthreads();
    return r;
}

// ---------------------------------------------------------------------------
// Kernel 1: masked per-channel sum over T + per-batch stats + PADDED-ROW
// ZERO-FILL. grid (NBLK_PER_B, B), 256 threads, 32 rows/block. Mask is a
// monotone prefix, so within this block rows [count, 32) are padding: this
// block zero-fills them in `out` (overlapped with its read phase), letting
// the output pass skip padding entirely. Ticketed last block computes
// k_centered and 1/kd, then restores scratch to zero for graph replay.
__global__ void __launch_bounds__(256) k_reduce_fused(
        const float4* __restrict__ x,
        const int* __restrict__ mask,
        float4* __restrict__ out) {
    const int b = blockIdx.y;
    const int t0 = blockIdx.x * ROWS_PER_BLK;
    const int tid = threadIdx.x;

    __shared__ int scount;
    __shared__ int slast;

    if (tid < 32) {
        int mv = mask[b * T_DIM + t0 + tid];
        unsigned bal = __ballot_sync(0xffffffffu, mv != 0);
        if (tid == 0) scount = __popc(bal);
    }
    __syncthreads();
    const int count = scount;

    const size_t rowbase = ((size_t)b * T_DIM + t0) * F4;

    if (count > 0) {
        const float4* xb = x + rowbase + tid;
        float ax = 0.f, ay = 0.f, az = 0.f, aw = 0.f;
        #pragma unroll 8
        for (int r = 0; r < count; ++r) {
            float4 v = xb[(size_t)r * F4];
            ax += v.x; ay += v.y; az += v.z; aw += v.w;
        }
        float* dst = &g_ksum[b * F_DIM + tid * 4];
        atomicAdd(dst + 0, ax);
        atomicAdd(dst + 1, ay);
        atomicAdd(dst + 2, az);
        atomicAdd(dst + 3, aw);
        if (tid == 0) atomicAdd(&g_len[b], count);
    }

    // Zero-fill this block's padded rows (rows [count, 32) of the window).
    {
        const float4 z = make_float4(0.f, 0.f, 0.f, 0.f);
        for (int r = count; r < ROWS_PER_BLK; ++r)
            __stcs(&out[rowbase + (size_t)r * F4 + tid], z);
    }

    // ---- completion ticket ----
    __threadfence();
    __syncthreads();
    if (tid == 0)
        slast = (atomicAdd(&g_done[b], 1) == NBLK_PER_B - 1) ? 1 : 0;
    __syncthreads();
    if (!slast) return;

    // ---- last block of this batch: per-batch stats ----
    const float L = (float)g_len[b];
    const float invL = 1.0f / L;

    float kv[4];
    float s = 0.f;
    #pragma unroll
    for (int j = 0; j < 4; ++j) {
        kv[j] = g_ksum[b * F_DIM + tid * 4 + j] * invL;
        s += kv[j];
    }
    float meank = block_reduce1(s) * (1.0f / (float)F_DIM);

    float ss = 0.f;
    #pragma unroll
    for (int j = 0; j < 4; ++j) {
        float kc = kv[j] - meank;
        g_kc[b * F_DIM + tid * 4 + j] = kc;
        ss += kc * kc;
        g_ksum[b * F_DIM + tid * 4 + j] = 0.0f;   // restore for next replay
    }
    float kd2 = block_reduce1(ss);
    if (tid == 0) {
        g_invkd[b] = rsqrtf(kd2);
        g_len[b] = 0;
        g_done[b] = 0;
    }
}

// ---------------------------------------------------------------------------
// Kernel 2: WARP-PER-ROW output over VALID rows only (padding already zeroed
// by kernel 1). Reverse global order to reuse the x tail kernel 1 left in L2.
// 48 regs, MLP=8 — best measured config.
__global__ void __launch_bounds__(256) pfsa_out_kernel(
        const float4* __restrict__ x,
        const int* __restrict__ mask,
        float4* __restrict__ out) {
    const int warp = threadIdx.x >> 5;
    const int lane = threadIdx.x & 31;

    const int row = (B_DIM * T_DIM - 1) - (blockIdx.x * 8 + warp);
    const int b = row >> 12;            // row / T_DIM
    const int t = row & (T_DIM - 1);    // row % T_DIM

    if (!mask[b * T_DIM + t]) return;   // padding handled in kernel 1

    const size_t base = (size_t)row * F4;

    // Front-batched x loads: 8 independent float4 (last use -> .cs)
    float4 v[8];
    #pragma unroll
    for (int j = 0; j < 8; ++j) v[j] = __ldcs(&x[base + lane + j * 32]);

    float s1 = 0.f, s2 = 0.f;
    #pragma unroll
    for (int j = 0; j < 8; ++j) {
        s1 += v[j].x + v[j].y + v[j].z + v[j].w;
        s2 += v[j].x * v[j].x + v[j].y * v[j].y + v[j].z * v[j].z + v[j].w * v[j].w;
    }

    // kc dot in two 4-wide chunks (kc: 4 KB/batch, L1/L2-resident)
    const float4* kcb = (const float4*)&g_kc[b * F_DIM];
    float s3 = 0.f;
    #pragma unroll
    for (int h = 0; h < 2; ++h) {
        float4 kc[4];
        #pragma unroll
        for (int j = 0; j < 4; ++j) kc[j] = kcb[lane + (h * 4 + j) * 32];
        #pragma unroll
        for (int j = 0; j < 4; ++j) {
            const float4& w = v[h * 4 + j];
            s3 += w.x * kc[j].x + w.y * kc[j].y + w.z * kc[j].z + w.w * kc[j].w;
        }
    }

    #pragma unroll
    for (int o = 16; o; o >>= 1) {
        s1 += __shfl_xor_sync(0xffffffffu, s1, o);
        s2 += __shfl_xor_sync(0xffffffffu, s2, o);
        s3 += __shfl_xor_sync(0xffffffffu, s3, o);
    }

    float qd2 = s2 - s1 * s1 * (1.0f / (float)F_DIM);
    float C = s3 * rsqrtf(qd2) * g_invkd[b];
    float A = 1.0f / (1.0f + __expf(C));   // (1 - sigmoid(C))^ALPHA, ALPHA=1

    #pragma unroll
    for (int j = 0; j < 8; ++j) {
        v[j].x *= A; v[j].y *= A; v[j].z *= A; v[j].w *= A;
        __stcs(&out[base + lane + j * 32], v[j]);
    }
}

// ---------------------------------------------------------------------------
extern "C" void kernel_launch(void* const* d_in, const int* in_sizes, int n_in,
                              void* d_out, int out_size) {
    const float4* x = (const float4*)d_in[0];
    const int* mask = (const int*)d_in[1];
    float4* out = (float4*)d_out;

    dim3 g1(NBLK_PER_B, B_DIM);
    k_reduce_fused<<<g1, 256>>>(x, mask, out);

    pfsa_out_kernel<<<(B_DIM * T_DIM) / 8, 256>>>(x, mask, out);
}